// round 12
// baseline (speedup 1.0000x reference)
#include <cuda_runtime.h>
#include <math.h>
#include <stdint.h>

#define B_ 2
#define S_ 2048
#define E_ 1024
#define H_ 16
#define D_ 64

// Scratch (allocation-free rule: __device__ globals)
__device__ float g_qkv[(size_t)B_ * S_ * 3 * E_];  // [B*S][3*E]  (tf32-rounded)
__device__ float g_att[(size_t)B_ * S_ * E_];      // [B*S][E]    (tf32-rounded)
__device__ float g_x [(size_t)B_ * S_ * E_];       // rounded x
__device__ float g_wq[(size_t)3 * E_ * E_];        // rounded qkv_w
__device__ float g_wp[(size_t)E_ * E_];            // rounded proj_w

// ---------------------------------------------------------------------------
// Helpers
// ---------------------------------------------------------------------------
__device__ __forceinline__ float tf32r(float x) {
    float r;
    asm("cvt.rna.tf32.f32 %0, %1;" : "=f"(r) : "f"(x));
    return r;
}
__device__ __forceinline__ uint32_t smem_u32(const void* p) {
    uint32_t a;
    asm("{ .reg .u64 t; cvta.to.shared.u64 t, %1; cvt.u32.u64 %0, t; }"
        : "=r"(a) : "l"(p));
    return a;
}
#define CPA16(dst, src) \
    asm volatile("cp.async.cg.shared.global [%0], [%1], 16;" :: "r"(dst), "l"(src) : "memory")
#define CPA_COMMIT() asm volatile("cp.async.commit_group;" ::: "memory")
#define CPA_WAIT0()  asm volatile("cp.async.wait_group 0;" ::: "memory")

#define MMA_TF32(d, a0, a1, a2, a3, b0, b1)                                   \
    asm volatile(                                                             \
        "mma.sync.aligned.m16n8k8.row.col.f32.tf32.tf32.f32 "                 \
        "{%0,%1,%2,%3},{%4,%5,%6,%7},{%8,%9},{%0,%1,%2,%3};"                  \
        : "+f"((d)[0]), "+f"((d)[1]), "+f"((d)[2]), "+f"((d)[3])              \
        : "r"(a0), "r"(a1), "r"(a2), "r"(a3), "r"(b0), "r"(b1))

// ---------------------------------------------------------------------------
// Prep: tf32-round three fp32 arrays in one launch
// ---------------------------------------------------------------------------
__global__ void round_copy3(const float* __restrict__ s0, float* __restrict__ d0, int n0,
                            const float* __restrict__ s1, float* __restrict__ d1, int n1,
                            const float* __restrict__ s2, float* __restrict__ d2, int n2)
{
    int i = blockIdx.x * blockDim.x + threadIdx.x;
    int stride = gridDim.x * blockDim.x;
    int ntot = n0 + n1 + n2;
    for (; i < ntot; i += stride) {
        const float4* src;
        float4* dst;
        int j = i;
        if (j < n0)              { src = (const float4*)s0; dst = (float4*)d0; }
        else if ((j -= n0) < n1) { src = (const float4*)s1; dst = (float4*)d1; }
        else                     { j -= n1; src = (const float4*)s2; dst = (float4*)d2; }
        float4 v = src[j];
        v.x = tf32r(v.x); v.y = tf32r(v.y); v.z = tf32r(v.z); v.w = tf32r(v.w);
        dst[j] = v;
    }
}

// ---------------------------------------------------------------------------
// GEMM v2 (unchanged from R11): 64x128 CTA tile, 32x32 warp tile, BK=32.
// ---------------------------------------------------------------------------
#define GS_STRIDE 36
#define GA_FLOATS (64 * GS_STRIDE)
#define GB_FLOATS (128 * GS_STRIDE)
#define G_OFF_A0 0
#define G_OFF_A1 GA_FLOATS
#define G_OFF_B0 (2 * GA_FLOATS)
#define G_OFF_B1 (2 * GA_FLOATS + GB_FLOATS)
#define G_SMEM_BYTES ((2 * GA_FLOATS + 2 * GB_FLOATS) * 4)   // 55,296 B

__global__ __launch_bounds__(256, 3) void gemm_tf32_v2(
    const float* __restrict__ A, const float* __restrict__ Bm,
    const float* __restrict__ bias, float* __restrict__ C,
    int M, int N, int K, int do_round)
{
    extern __shared__ float smg[];
    const uint32_t sb = smem_u32(smg);

    const int tid  = threadIdx.x;
    const int warp = tid >> 5;
    const int lane = tid & 31;
    const int m0 = blockIdx.y * 64;
    const int n0 = blockIdx.x * 128;
    const int wm = (warp >> 2) * 32;
    const int wn = (warp & 3) * 32;
    const int r  = lane >> 2;
    const int cq = lane & 3;

    const int srow = tid >> 3;
    const int svec = tid & 7;

    float acc[2][4][4] = {};
    const int T = K >> 5;

#define GEMM_STAGE(t, buf) do {                                               \
        const int k0_ = (t) << 5;                                             \
        uint32_t abase = sb + ((buf) ? G_OFF_A1 : G_OFF_A0) * 4;              \
        uint32_t bbase = sb + ((buf) ? G_OFF_B1 : G_OFF_B0) * 4;              \
        _Pragma("unroll")                                                     \
        for (int u = 0; u < 2; ++u) {                                         \
            int row = srow + u * 32;                                          \
            uint32_t da = abase + (row * GS_STRIDE + svec * 4) * 4;           \
            CPA16(da, A + (size_t)(m0 + row) * K + k0_ + svec * 4);           \
        }                                                                     \
        _Pragma("unroll")                                                     \
        for (int u = 0; u < 4; ++u) {                                         \
            int row = srow + u * 32;                                          \
            uint32_t db = bbase + (row * GS_STRIDE + svec * 4) * 4;           \
            CPA16(db, Bm + (size_t)(n0 + row) * K + k0_ + svec * 4);          \
        }                                                                     \
    } while (0)

    GEMM_STAGE(0, 0);
    CPA_COMMIT();
    CPA_WAIT0();
    __syncthreads();

    for (int t = 0; t < T; ++t) {
        const int buf = t & 1;
        if (t + 1 < T) {
            GEMM_STAGE(t + 1, buf ^ 1);
            CPA_COMMIT();
        }

        const float* Asb = smg + (buf ? G_OFF_A1 : G_OFF_A0);
        const float* Bsb = smg + (buf ? G_OFF_B1 : G_OFF_B0);
#pragma unroll
        for (int ks = 0; ks < 4; ++ks) {
            const int kk = ks * 8 + cq;
            unsigned a[2][4], b[4][2];
#pragma unroll
            for (int mt = 0; mt < 2; ++mt) {
                int row = wm + mt * 16 + r;
                a[mt][0] = __float_as_uint(Asb[row * GS_STRIDE + kk]);
                a[mt][1] = __float_as_uint(Asb[(row + 8) * GS_STRIDE + kk]);
                a[mt][2] = __float_as_uint(Asb[row * GS_STRIDE + kk + 4]);
                a[mt][3] = __float_as_uint(Asb[(row + 8) * GS_STRIDE + kk + 4]);
            }
#pragma unroll
            for (int nt = 0; nt < 4; ++nt) {
                int col = wn + nt * 8 + r;
                b[nt][0] = __float_as_uint(Bsb[col * GS_STRIDE + kk]);
                b[nt][1] = __float_as_uint(Bsb[col * GS_STRIDE + kk + 4]);
            }
#pragma unroll
            for (int mt = 0; mt < 2; ++mt)
#pragma unroll
                for (int nt = 0; nt < 4; ++nt)
                    MMA_TF32(acc[mt][nt], a[mt][0], a[mt][1], a[mt][2], a[mt][3],
                             b[nt][0], b[nt][1]);
        }

        if (t + 1 < T) {
            CPA_WAIT0();
            __syncthreads();
        }
    }
#undef GEMM_STAGE

    const int c2 = cq * 2;
#pragma unroll
    for (int nt = 0; nt < 4; ++nt) {
        int col = n0 + wn + nt * 8 + c2;
        float b0 = bias[col], b1 = bias[col + 1];
#pragma unroll
        for (int mt = 0; mt < 2; ++mt) {
            int row = m0 + wm + mt * 16 + r;
            float v00 = acc[mt][nt][0] + b0, v01 = acc[mt][nt][1] + b1;
            float v10 = acc[mt][nt][2] + b0, v11 = acc[mt][nt][3] + b1;
            if (do_round) {
                v00 = tf32r(v00); v01 = tf32r(v01);
                v10 = tf32r(v10); v11 = tf32r(v11);
            }
            *(float2*)(C + (size_t)row * N + col)       = make_float2(v00, v01);
            *(float2*)(C + (size_t)(row + 8) * N + col) = make_float2(v10, v11);
        }
    }
}

// ---------------------------------------------------------------------------
// Flash attention v5: 128 q-rows per CTA, 256 threads = 8 warps x 16 rows.
// 64-key double-buffered stages, register softmax, Q-fragment hoist,
// one sync per stage. smem 105 KB -> 2 CTAs/SM: cross-CTA overlap hides
// the softmax serial chain.
// ---------------------------------------------------------------------------
#define FKV 68
#define FQ_FLOATS  (128 * FKV)                  // 8704
#define FKV_FLOATS (64 * FKV)                   // 4352 per buf per matrix
#define OFF_K  FQ_FLOATS
#define OFF_V  (FQ_FLOATS + 2 * FKV_FLOATS)
#define OFF_MK (FQ_FLOATS + 4 * FKV_FLOATS)
#define FA_SMEM_BYTES ((OFF_MK + 2 * 64) * 4)   // 104,960 B

__global__ __launch_bounds__(256, 2) void flash_attn_v5(const int* __restrict__ mask)
{
    extern __shared__ float sm[];
    const uint32_t sb = smem_u32(sm);

    const int tid  = threadIdx.x;
    const int warp = tid >> 5;
    const int lane = tid & 31;
    const int q0 = blockIdx.x * 128;
    const int h  = blockIdx.y;
    const int b  = blockIdx.z;
    const int wq = warp * 16;
    const int r  = lane >> 2;
    const int cq = lane & 3;
    const int qrow = wq + r;

    const size_t rowstride = (size_t)3 * E_;

    // ---- Stage Q (128 x 64): 2048 cp16, 8 per thread ----
    {
        const float* qb = g_qkv + (size_t)(b * S_ + q0) * rowstride + h * D_;
#pragma unroll
        for (int u = 0; u < 8; ++u) {
            int idx = tid + u * 256;
            int row = idx >> 4;
            int vec = idx & 15;
            uint32_t dq = sb + (row * FKV + vec * 4) * 4;
            CPA16(dq, qb + (size_t)row * rowstride + vec * 4);
        }
    }

    // ---- 64-key stage: 1024 cp16 per matrix, 4 per thread per matrix ----
#define FA_STAGE(t, buf) do {                                                 \
        const int k0_ = (t) * 64;                                             \
        const float* kb = g_qkv + (size_t)(b * S_ + k0_) * rowstride + E_ + h * D_; \
        _Pragma("unroll")                                                     \
        for (int u = 0; u < 4; ++u) {                                         \
            int idx = tid + u * 256;                                          \
            int row = idx >> 4;                                               \
            int vec = idx & 15;                                               \
            uint32_t dk = sb + ((OFF_K + (buf) * FKV_FLOATS) + row * FKV + vec * 4) * 4; \
            CPA16(dk, kb + (size_t)row * rowstride + vec * 4);                \
            uint32_t dv = sb + ((OFF_V + (buf) * FKV_FLOATS) + row * FKV + vec * 4) * 4; \
            CPA16(dv, kb + E_ + (size_t)row * rowstride + vec * 4);           \
        }                                                                     \
        if (tid < 64)                                                         \
            sm[OFF_MK + (buf) * 64 + tid] =                                   \
                mask[b * S_ + k0_ + tid] ? 0.f : -INFINITY;                   \
    } while (0)

    FA_STAGE(0, 0);
    CPA_COMMIT();
    CPA_WAIT0();
    __syncthreads();

    // ---- Hoist Q fragments (loop-invariant): 32 regs ----
    unsigned qa[8][4];
#pragma unroll
    for (int ks = 0; ks < 8; ++ks) {
        const int kk = ks * 8 + cq;
        qa[ks][0] = __float_as_uint(sm[qrow * FKV + kk]);
        qa[ks][1] = __float_as_uint(sm[(qrow + 8) * FKV + kk]);
        qa[ks][2] = __float_as_uint(sm[qrow * FKV + kk + 4]);
        qa[ks][3] = __float_as_uint(sm[(qrow + 8) * FKV + kk + 4]);
    }

    float o[8][4] = {};
    float m0 = -INFINITY, m1 = -INFINITY, l0 = 0.f, l1 = 0.f;

    const int T = S_ / 64;
    for (int t = 0; t < T; ++t) {
        const int buf = t & 1;
        if (t + 1 < T) {
            FA_STAGE(t + 1, buf ^ 1);
            CPA_COMMIT();
        }

        const float* Ksb = sm + OFF_K + buf * FKV_FLOATS;
        const float* Vsb = sm + OFF_V + buf * FKV_FLOATS;
        const float* mkb = sm + OFF_MK + buf * 64;

        // ---- S = Q K^T ----
        float s[8][4] = {};
#pragma unroll
        for (int ks = 0; ks < 8; ++ks) {
            const int kk = ks * 8 + cq;
#pragma unroll
            for (int nt = 0; nt < 8; ++nt) {
                unsigned b0 = __float_as_uint(Ksb[(nt * 8 + r) * FKV + kk]);
                unsigned b1 = __float_as_uint(Ksb[(nt * 8 + r) * FKV + kk + 4]);
                MMA_TF32(s[nt], qa[ks][0], qa[ks][1], qa[ks][2], qa[ks][3], b0, b1);
            }
        }

        // ---- scale 1/8 + mask ----
#pragma unroll
        for (int nt = 0; nt < 8; ++nt) {
            float mk0 = mkb[nt * 8 + 2 * cq];
            float mk1 = mkb[nt * 8 + 2 * cq + 1];
            s[nt][0] = fmaf(s[nt][0], 0.125f, mk0);
            s[nt][1] = fmaf(s[nt][1], 0.125f, mk1);
            s[nt][2] = fmaf(s[nt][2], 0.125f, mk0);
            s[nt][3] = fmaf(s[nt][3], 0.125f, mk1);
        }

        // ---- register online softmax (rows r, r+8) ----
        float mx0 = -INFINITY, mx1 = -INFINITY;
#pragma unroll
        for (int nt = 0; nt < 8; ++nt) {
            mx0 = fmaxf(mx0, fmaxf(s[nt][0], s[nt][1]));
            mx1 = fmaxf(mx1, fmaxf(s[nt][2], s[nt][3]));
        }
        mx0 = fmaxf(mx0, __shfl_xor_sync(0xffffffffu, mx0, 1));
        mx0 = fmaxf(mx0, __shfl_xor_sync(0xffffffffu, mx0, 2));
        mx1 = fmaxf(mx1, __shfl_xor_sync(0xffffffffu, mx1, 1));
        mx1 = fmaxf(mx1, __shfl_xor_sync(0xffffffffu, mx1, 2));

        float mn0 = fmaxf(m0, mx0);
        float mn1 = fmaxf(m1, mx1);
        float al0 = 1.f, al1 = 1.f;
        float ls0 = 0.f, ls1 = 0.f;
        if (mn0 != -INFINITY) {
            al0 = __expf(m0 - mn0);
#pragma unroll
            for (int nt = 0; nt < 8; ++nt) {
                float p0 = __expf(s[nt][0] - mn0);
                float p1 = __expf(s[nt][1] - mn0);
                ls0 += p0 + p1;
                s[nt][0] = tf32r(p0);
                s[nt][1] = tf32r(p1);
            }
        } else {
#pragma unroll
            for (int nt = 0; nt < 8; ++nt) { s[nt][0] = 0.f; s[nt][1] = 0.f; }
        }
        if (mn1 != -INFINITY) {
            al1 = __expf(m1 - mn1);
#pragma unroll
            for (int nt = 0; nt < 8; ++nt) {
                float p2 = __expf(s[nt][2] - mn1);
                float p3 = __expf(s[nt][3] - mn1);
                ls1 += p2 + p3;
                s[nt][2] = tf32r(p2);
                s[nt][3] = tf32r(p3);
            }
        } else {
#pragma unroll
            for (int nt = 0; nt < 8; ++nt) { s[nt][2] = 0.f; s[nt][3] = 0.f; }
        }
        ls0 += __shfl_xor_sync(0xffffffffu, ls0, 1);
        ls0 += __shfl_xor_sync(0xffffffffu, ls0, 2);
        ls1 += __shfl_xor_sync(0xffffffffu, ls1, 1);
        ls1 += __shfl_xor_sync(0xffffffffu, ls1, 2);

        l0 = l0 * al0 + ls0;  m0 = mn0;
        l1 = l1 * al1 + ls1;  m1 = mn1;

#pragma unroll
        for (int nt = 0; nt < 8; ++nt) {
            o[nt][0] *= al0; o[nt][1] *= al0;
            o[nt][2] *= al1; o[nt][3] *= al1;
        }

        // ---- O += P V ----
#pragma unroll
        for (int ks = 0; ks < 8; ++ks) {
            unsigned pa0 = __float_as_uint(s[ks][0]);
            unsigned pa1 = __float_as_uint(s[ks][2]);
            unsigned pa2 = __float_as_uint(s[ks][1]);
            unsigned pa3 = __float_as_uint(s[ks][3]);
            const float* vrow0 = Vsb + (ks * 8 + 2 * cq) * FKV;
#pragma unroll
            for (int nt = 0; nt < 8; ++nt) {
                unsigned vb0 = __float_as_uint(vrow0[nt * 8 + r]);
                unsigned vb1 = __float_as_uint(vrow0[FKV + nt * 8 + r]);
                MMA_TF32(o[nt], pa0, pa1, pa2, pa3, vb0, vb1);
            }
        }

        if (t + 1 < T) {
            CPA_WAIT0();
            __syncthreads();
        }
    }
#undef FA_STAGE

    // ---- normalize + tf32 round + store ----
    float inv0 = (l0 > 0.f) ? (1.f / l0) : 0.f;
    float inv1 = (l1 > 0.f) ? (1.f / l1) : 0.f;
    float* d0 = g_att + (size_t)(b * S_ + q0 + qrow) * E_ + h * D_;
    float* d1 = g_att + (size_t)(b * S_ + q0 + qrow + 8) * E_ + h * D_;
#pragma unroll
    for (int nt = 0; nt < 8; ++nt) {
        int col = nt * 8 + 2 * cq;
        *(float2*)(d0 + col) = make_float2(tf32r(o[nt][0] * inv0), tf32r(o[nt][1] * inv0));
        *(float2*)(d1 + col) = make_float2(tf32r(o[nt][2] * inv1), tf32r(o[nt][3] * inv1));
    }
}

// ---------------------------------------------------------------------------
extern "C" void kernel_launch(void* const* d_in, const int* in_sizes, int n_in,
                              void* d_out, int out_size)
{
    const float* x      = (const float*)d_in[0];
    const int*   mask   = (const int*)d_in[1];
    const float* qkv_w  = (const float*)d_in[2];
    const float* qkv_b  = (const float*)d_in[3];
    const float* proj_w = (const float*)d_in[4];
    const float* proj_b = (const float*)d_in[5];
    float* out = (float*)d_out;

    float *qkv_p, *att_p, *x_p, *wq_p, *wp_p;
    cudaGetSymbolAddress((void**)&qkv_p, g_qkv);
    cudaGetSymbolAddress((void**)&att_p, g_att);
    cudaGetSymbolAddress((void**)&x_p,  g_x);
    cudaGetSymbolAddress((void**)&wq_p, g_wq);
    cudaGetSymbolAddress((void**)&wp_p, g_wp);

    cudaFuncSetAttribute(gemm_tf32_v2, cudaFuncAttributeMaxDynamicSharedMemorySize,
                         G_SMEM_BYTES);
    cudaFuncSetAttribute(gemm_tf32_v2, cudaFuncAttributePreferredSharedMemoryCarveout,
                         100);
    cudaFuncSetAttribute(flash_attn_v5, cudaFuncAttributeMaxDynamicSharedMemorySize,
                         FA_SMEM_BYTES);

    // 0) Pre-round inputs to tf32 scratch (one launch)
    round_copy3<<<512, 256>>>(x, x_p, B_ * S_ * E_ / 4,
                              qkv_w, wq_p, 3 * E_ * E_ / 4,
                              proj_w, wp_p, E_ * E_ / 4);

    // 1) QKV GEMM: [4096,1024] x [3072,1024]^T -> [4096,3072]
    gemm_tf32_v2<<<dim3(3 * E_ / 128, B_ * S_ / 64), 256, G_SMEM_BYTES>>>(
        x_p, wq_p, qkv_b, qkv_p, B_ * S_, 3 * E_, E_, 1);

    // 2) Flash attention -> g_att (tf32-rounded)
    flash_attn_v5<<<dim3(S_ / 128, H_, B_), 256, FA_SMEM_BYTES>>>(mask);

    // 3) Proj GEMM: [4096,1024] x [1024,1024]^T -> out
    gemm_tf32_v2<<<dim3(E_ / 128, B_ * S_ / 64), 256, G_SMEM_BYTES>>>(
        att_p, wp_p, proj_b, out, B_ * S_, E_, E_, 0);
}

// round 13
// speedup vs baseline: 1.0541x; 1.0541x over previous
#include <cuda_runtime.h>
#include <math.h>
#include <stdint.h>

#define B_ 2
#define S_ 2048
#define E_ 1024
#define H_ 16
#define D_ 64

// Scratch (allocation-free rule: __device__ globals)
// g_x/g_wq/g_wp: tf32-rounded + 8-group k-permuted [0,4,1,5,2,6,3,7]
// g_qkv: logical layout (GEMM output), tf32-rounded
// g_att: tf32-rounded + k-permuted columns (proj's A operand)
__device__ float g_qkv[(size_t)B_ * S_ * 3 * E_];
__device__ float g_att[(size_t)B_ * S_ * E_];
__device__ float g_x [(size_t)B_ * S_ * E_];
__device__ float g_wq[(size_t)3 * E_ * E_];
__device__ float g_wp[(size_t)E_ * E_];

// ---------------------------------------------------------------------------
// Helpers
// ---------------------------------------------------------------------------
__device__ __forceinline__ float tf32r(float x) {
    float r;
    asm("cvt.rna.tf32.f32 %0, %1;" : "=f"(r) : "f"(x));
    return r;
}
__device__ __forceinline__ uint32_t smem_u32(const void* p) {
    uint32_t a;
    asm("{ .reg .u64 t; cvta.to.shared.u64 t, %1; cvt.u32.u64 %0, t; }"
        : "=r"(a) : "l"(p));
    return a;
}
// position of logical column c (0..7) within permuted 8-group storage
__device__ __forceinline__ int kperm(int c) {
    return (c < 4) ? (2 * c) : (2 * (c - 4) + 1);
}
#define CPA16(dst, src) \
    asm volatile("cp.async.cg.shared.global [%0], [%1], 16;" :: "r"(dst), "l"(src) : "memory")
#define CPA_COMMIT() asm volatile("cp.async.commit_group;" ::: "memory")
#define CPA_WAIT0()  asm volatile("cp.async.wait_group 0;" ::: "memory")

#define MMA_TF32(d, a0, a1, a2, a3, b0, b1)                                   \
    asm volatile(                                                             \
        "mma.sync.aligned.m16n8k8.row.col.f32.tf32.tf32.f32 "                 \
        "{%0,%1,%2,%3},{%4,%5,%6,%7},{%8,%9},{%0,%1,%2,%3};"                  \
        : "+f"((d)[0]), "+f"((d)[1]), "+f"((d)[2]), "+f"((d)[3])              \
        : "r"(a0), "r"(a1), "r"(a2), "r"(a3), "r"(b0), "r"(b1))

// ---------------------------------------------------------------------------
// Prep: tf32-round + 8-group k-permute, three arrays in one launch.
// out[8i+{0..7}] = rnd(in[8i+{0,4,1,5,2,6,3,7}])
// ---------------------------------------------------------------------------
__global__ void round_perm3(const float* __restrict__ s0, float* __restrict__ d0, int n0,
                            const float* __restrict__ s1, float* __restrict__ d1, int n1,
                            const float* __restrict__ s2, float* __restrict__ d2, int n2)
{
    int i = blockIdx.x * blockDim.x + threadIdx.x;
    int stride = gridDim.x * blockDim.x;
    int ntot = n0 + n1 + n2;   // counts in 8-float groups
    for (; i < ntot; i += stride) {
        const float4* src;
        float4* dst;
        int j = i;
        if (j < n0)              { src = (const float4*)s0; dst = (float4*)d0; }
        else if ((j -= n0) < n1) { src = (const float4*)s1; dst = (float4*)d1; }
        else                     { j -= n1; src = (const float4*)s2; dst = (float4*)d2; }
        float4 u = src[2 * j];       // k0..k3
        float4 v = src[2 * j + 1];   // k4..k7
        u.x = tf32r(u.x); u.y = tf32r(u.y); u.z = tf32r(u.z); u.w = tf32r(u.w);
        v.x = tf32r(v.x); v.y = tf32r(v.y); v.z = tf32r(v.z); v.w = tf32r(v.w);
        dst[2 * j]     = make_float4(u.x, v.x, u.y, v.y);
        dst[2 * j + 1] = make_float4(u.z, v.z, u.w, v.w);
    }
}

// ---------------------------------------------------------------------------
// GEMM v3: 64x128 CTA tile, 32x32 warp tile, BK=32, 3 CTAs/SM.
// Inputs k-permuted -> fragment loads are LDS.64 (half the LDS count).
// cp.async double buffer, one sync per k-tile. Outputs logical columns.
// ---------------------------------------------------------------------------
#define GS_STRIDE 40
#define GA_FLOATS (64 * GS_STRIDE)     // 2560 per buffer
#define GB_FLOATS (128 * GS_STRIDE)    // 5120 per buffer
#define G_OFF_A0 0
#define G_OFF_A1 GA_FLOATS
#define G_OFF_B0 (2 * GA_FLOATS)
#define G_OFF_B1 (2 * GA_FLOATS + GB_FLOATS)
#define G_SMEM_BYTES ((2 * GA_FLOATS + 2 * GB_FLOATS) * 4)   // 61,440 B

__global__ __launch_bounds__(256, 3) void gemm_tf32_v3(
    const float* __restrict__ A, const float* __restrict__ Bm,
    const float* __restrict__ bias, float* __restrict__ C,
    int M, int N, int K, int do_round)
{
    extern __shared__ float smg[];
    const uint32_t sb = smem_u32(smg);

    const int tid  = threadIdx.x;
    const int warp = tid >> 5;
    const int lane = tid & 31;
    const int m0 = blockIdx.y * 64;
    const int n0 = blockIdx.x * 128;
    const int wm = (warp >> 2) * 32;
    const int wn = (warp & 3) * 32;
    const int r  = lane >> 2;
    const int cq = lane & 3;

    const int srow = tid >> 3;
    const int svec = tid & 7;

    float acc[2][4][4] = {};
    const int T = K >> 5;

#define GEMM_STAGE(t, buf) do {                                               \
        const int k0_ = (t) << 5;                                             \
        uint32_t abase = sb + ((buf) ? G_OFF_A1 : G_OFF_A0) * 4;              \
        uint32_t bbase = sb + ((buf) ? G_OFF_B1 : G_OFF_B0) * 4;              \
        _Pragma("unroll")                                                     \
        for (int u = 0; u < 2; ++u) {                                         \
            int row = srow + u * 32;                                          \
            uint32_t da = abase + (row * GS_STRIDE + svec * 4) * 4;           \
            CPA16(da, A + (size_t)(m0 + row) * K + k0_ + svec * 4);           \
        }                                                                     \
        _Pragma("unroll")                                                     \
        for (int u = 0; u < 4; ++u) {                                         \
            int row = srow + u * 32;                                          \
            uint32_t db = bbase + (row * GS_STRIDE + svec * 4) * 4;           \
            CPA16(db, Bm + (size_t)(n0 + row) * K + k0_ + svec * 4);          \
        }                                                                     \
    } while (0)

    GEMM_STAGE(0, 0);
    CPA_COMMIT();
    CPA_WAIT0();
    __syncthreads();

    for (int t = 0; t < T; ++t) {
        const int buf = t & 1;
        if (t + 1 < T) {
            GEMM_STAGE(t + 1, buf ^ 1);
            CPA_COMMIT();
        }

        const float* Asb = smg + (buf ? G_OFF_A1 : G_OFF_A0);
        const float* Bsb = smg + (buf ? G_OFF_B1 : G_OFF_B0);
#pragma unroll
        for (int ks = 0; ks < 4; ++ks) {
            const int kb2 = ks * 8 + 2 * cq;     // permuted: (kk, kk+4) adjacent
            unsigned a[2][4], b[4][2];
#pragma unroll
            for (int mt = 0; mt < 2; ++mt) {
                int row = wm + mt * 16 + r;
                float2 f0 = *(const float2*)&Asb[row * GS_STRIDE + kb2];
                float2 f1 = *(const float2*)&Asb[(row + 8) * GS_STRIDE + kb2];
                a[mt][0] = __float_as_uint(f0.x);
                a[mt][1] = __float_as_uint(f1.x);
                a[mt][2] = __float_as_uint(f0.y);
                a[mt][3] = __float_as_uint(f1.y);
            }
#pragma unroll
            for (int nt = 0; nt < 4; ++nt) {
                float2 f = *(const float2*)&Bsb[(wn + nt * 8 + r) * GS_STRIDE + kb2];
                b[nt][0] = __float_as_uint(f.x);
                b[nt][1] = __float_as_uint(f.y);
            }
#pragma unroll
            for (int mt = 0; mt < 2; ++mt)
#pragma unroll
                for (int nt = 0; nt < 4; ++nt)
                    MMA_TF32(acc[mt][nt], a[mt][0], a[mt][1], a[mt][2], a[mt][3],
                             b[nt][0], b[nt][1]);
        }

        if (t + 1 < T) {
            CPA_WAIT0();
            __syncthreads();
        }
    }
#undef GEMM_STAGE

    const int c2 = cq * 2;
#pragma unroll
    for (int nt = 0; nt < 4; ++nt) {
        int col = n0 + wn + nt * 8 + c2;
        float b0 = bias[col], b1 = bias[col + 1];
#pragma unroll
        for (int mt = 0; mt < 2; ++mt) {
            int row = m0 + wm + mt * 16 + r;
            float v00 = acc[mt][nt][0] + b0, v01 = acc[mt][nt][1] + b1;
            float v10 = acc[mt][nt][2] + b0, v11 = acc[mt][nt][3] + b1;
            if (do_round) {
                v00 = tf32r(v00); v01 = tf32r(v01);
                v10 = tf32r(v10); v11 = tf32r(v11);
            }
            *(float2*)(C + (size_t)row * N + col)       = make_float2(v00, v01);
            *(float2*)(C + (size_t)(row + 8) * N + col) = make_float2(v10, v11);
        }
    }
}

// ---------------------------------------------------------------------------
// Flash attention v4 (R11's proven version): 256 q-rows, 512 threads,
// 128-key stages as two 64-key halves, register softmax, Q-fragment hoist.
// ONLY change: epilogue writes g_att with k-permuted columns (proj input).
// ---------------------------------------------------------------------------
#define FKV 68
#define FQ_FLOATS  (256 * FKV)
#define FKV_FLOATS (128 * FKV)
#define OFF_K  FQ_FLOATS
#define OFF_V  (FQ_FLOATS + 2 * FKV_FLOATS)
#define OFF_MK (FQ_FLOATS + 4 * FKV_FLOATS)
#define FA_SMEM_BYTES ((OFF_MK + 2 * 128) * 4)  // 209,920 B

__global__ __launch_bounds__(512, 1) void flash_attn_v4(const int* __restrict__ mask)
{
    extern __shared__ float sm[];
    const uint32_t sb = smem_u32(sm);

    const int tid  = threadIdx.x;
    const int warp = tid >> 5;
    const int lane = tid & 31;
    const int q0 = blockIdx.x * 256;
    const int h  = blockIdx.y;
    const int b  = blockIdx.z;
    const int wq = warp * 16;
    const int r  = lane >> 2;
    const int cq = lane & 3;
    const int qrow = wq + r;

    const size_t rowstride = (size_t)3 * E_;

    {
        const float* qb = g_qkv + (size_t)(b * S_ + q0) * rowstride + h * D_;
#pragma unroll
        for (int u = 0; u < 8; ++u) {
            int idx = tid + u * 512;
            int row = idx >> 4;
            int vec = idx & 15;
            uint32_t dq = sb + (row * FKV + vec * 4) * 4;
            CPA16(dq, qb + (size_t)row * rowstride + vec * 4);
        }
    }

#define FA_STAGE(t, buf) do {                                                 \
        const int k0_ = (t) * 128;                                            \
        const float* kb = g_qkv + (size_t)(b * S_ + k0_) * rowstride + E_ + h * D_; \
        _Pragma("unroll")                                                     \
        for (int u = 0; u < 4; ++u) {                                         \
            int idx = tid + u * 512;                                          \
            int row = idx >> 4;                                               \
            int vec = idx & 15;                                               \
            uint32_t dk = sb + ((OFF_K + (buf) * FKV_FLOATS) + row * FKV + vec * 4) * 4; \
            CPA16(dk, kb + (size_t)row * rowstride + vec * 4);                \
            uint32_t dv = sb + ((OFF_V + (buf) * FKV_FLOATS) + row * FKV + vec * 4) * 4; \
            CPA16(dv, kb + E_ + (size_t)row * rowstride + vec * 4);           \
        }                                                                     \
        if (tid < 128)                                                        \
            sm[OFF_MK + (buf) * 128 + tid] =                                  \
                mask[b * S_ + k0_ + tid] ? 0.f : -INFINITY;                   \
    } while (0)

    FA_STAGE(0, 0);
    CPA_COMMIT();
    CPA_WAIT0();
    __syncthreads();

    unsigned qa[8][4];
#pragma unroll
    for (int ks = 0; ks < 8; ++ks) {
        const int kk = ks * 8 + cq;
        qa[ks][0] = __float_as_uint(sm[qrow * FKV + kk]);
        qa[ks][1] = __float_as_uint(sm[(qrow + 8) * FKV + kk]);
        qa[ks][2] = __float_as_uint(sm[qrow * FKV + kk + 4]);
        qa[ks][3] = __float_as_uint(sm[(qrow + 8) * FKV + kk + 4]);
    }

    float o[8][4] = {};
    float m0 = -INFINITY, m1 = -INFINITY, l0 = 0.f, l1 = 0.f;

    const int T = S_ / 128;
    for (int t = 0; t < T; ++t) {
        const int buf = t & 1;
        if (t + 1 < T) {
            FA_STAGE(t + 1, buf ^ 1);
            CPA_COMMIT();
        }

#pragma unroll
        for (int half = 0; half < 2; ++half) {
            const float* Ksb = sm + OFF_K + buf * FKV_FLOATS + (half * 64) * FKV;
            const float* Vsb = sm + OFF_V + buf * FKV_FLOATS + (half * 64) * FKV;
            const float* mkb = sm + OFF_MK + buf * 128 + half * 64;

            float s[8][4] = {};
#pragma unroll
            for (int ks = 0; ks < 8; ++ks) {
                const int kk = ks * 8 + cq;
#pragma unroll
                for (int nt = 0; nt < 8; ++nt) {
                    unsigned b0 = __float_as_uint(Ksb[(nt * 8 + r) * FKV + kk]);
                    unsigned b1 = __float_as_uint(Ksb[(nt * 8 + r) * FKV + kk + 4]);
                    MMA_TF32(s[nt], qa[ks][0], qa[ks][1], qa[ks][2], qa[ks][3], b0, b1);
                }
            }

#pragma unroll
            for (int nt = 0; nt < 8; ++nt) {
                float mk0 = mkb[nt * 8 + 2 * cq];
                float mk1 = mkb[nt * 8 + 2 * cq + 1];
                s[nt][0] = fmaf(s[nt][0], 0.125f, mk0);
                s[nt][1] = fmaf(s[nt][1], 0.125f, mk1);
                s[nt][2] = fmaf(s[nt][2], 0.125f, mk0);
                s[nt][3] = fmaf(s[nt][3], 0.125f, mk1);
            }

            float mx0 = -INFINITY, mx1 = -INFINITY;
#pragma unroll
            for (int nt = 0; nt < 8; ++nt) {
                mx0 = fmaxf(mx0, fmaxf(s[nt][0], s[nt][1]));
                mx1 = fmaxf(mx1, fmaxf(s[nt][2], s[nt][3]));
            }
            mx0 = fmaxf(mx0, __shfl_xor_sync(0xffffffffu, mx0, 1));
            mx0 = fmaxf(mx0, __shfl_xor_sync(0xffffffffu, mx0, 2));
            mx1 = fmaxf(mx1, __shfl_xor_sync(0xffffffffu, mx1, 1));
            mx1 = fmaxf(mx1, __shfl_xor_sync(0xffffffffu, mx1, 2));

            float mn0 = fmaxf(m0, mx0);
            float mn1 = fmaxf(m1, mx1);
            float al0 = 1.f, al1 = 1.f;
            float ls0 = 0.f, ls1 = 0.f;
            if (mn0 != -INFINITY) {
                al0 = __expf(m0 - mn0);
#pragma unroll
                for (int nt = 0; nt < 8; ++nt) {
                    float p0 = __expf(s[nt][0] - mn0);
                    float p1 = __expf(s[nt][1] - mn0);
                    ls0 += p0 + p1;
                    s[nt][0] = tf32r(p0);
                    s[nt][1] = tf32r(p1);
                }
            } else {
#pragma unroll
                for (int nt = 0; nt < 8; ++nt) { s[nt][0] = 0.f; s[nt][1] = 0.f; }
            }
            if (mn1 != -INFINITY) {
                al1 = __expf(m1 - mn1);
#pragma unroll
                for (int nt = 0; nt < 8; ++nt) {
                    float p2 = __expf(s[nt][2] - mn1);
                    float p3 = __expf(s[nt][3] - mn1);
                    ls1 += p2 + p3;
                    s[nt][2] = tf32r(p2);
                    s[nt][3] = tf32r(p3);
                }
            } else {
#pragma unroll
                for (int nt = 0; nt < 8; ++nt) { s[nt][2] = 0.f; s[nt][3] = 0.f; }
            }
            ls0 += __shfl_xor_sync(0xffffffffu, ls0, 1);
            ls0 += __shfl_xor_sync(0xffffffffu, ls0, 2);
            ls1 += __shfl_xor_sync(0xffffffffu, ls1, 1);
            ls1 += __shfl_xor_sync(0xffffffffu, ls1, 2);

            l0 = l0 * al0 + ls0;  m0 = mn0;
            l1 = l1 * al1 + ls1;  m1 = mn1;

#pragma unroll
            for (int nt = 0; nt < 8; ++nt) {
                o[nt][0] *= al0; o[nt][1] *= al0;
                o[nt][2] *= al1; o[nt][3] *= al1;
            }

#pragma unroll
            for (int ks = 0; ks < 8; ++ks) {
                unsigned pa0 = __float_as_uint(s[ks][0]);
                unsigned pa1 = __float_as_uint(s[ks][2]);
                unsigned pa2 = __float_as_uint(s[ks][1]);
                unsigned pa3 = __float_as_uint(s[ks][3]);
                const float* vrow0 = Vsb + (ks * 8 + 2 * cq) * FKV;
#pragma unroll
                for (int nt = 0; nt < 8; ++nt) {
                    unsigned vb0 = __float_as_uint(vrow0[nt * 8 + r]);
                    unsigned vb1 = __float_as_uint(vrow0[FKV + nt * 8 + r]);
                    MMA_TF32(o[nt], pa0, pa1, pa2, pa3, vb0, vb1);
                }
            }
        }

        if (t + 1 < T) {
            CPA_WAIT0();
            __syncthreads();
        }
    }
#undef FA_STAGE

    // ---- normalize + tf32 round + store (k-permuted columns for proj) ----
    float inv0 = (l0 > 0.f) ? (1.f / l0) : 0.f;
    float inv1 = (l1 > 0.f) ? (1.f / l1) : 0.f;
    float* d0 = g_att + (size_t)(b * S_ + q0 + qrow) * E_ + h * D_;
    float* d1 = g_att + (size_t)(b * S_ + q0 + qrow + 8) * E_ + h * D_;
    const int pp0 = kperm(2 * cq);
    const int pp1 = kperm(2 * cq + 1);
#pragma unroll
    for (int nt = 0; nt < 8; ++nt) {
        d0[nt * 8 + pp0] = tf32r(o[nt][0] * inv0);
        d0[nt * 8 + pp1] = tf32r(o[nt][1] * inv0);
        d1[nt * 8 + pp0] = tf32r(o[nt][2] * inv1);
        d1[nt * 8 + pp1] = tf32r(o[nt][3] * inv1);
    }
}

// ---------------------------------------------------------------------------
extern "C" void kernel_launch(void* const* d_in, const int* in_sizes, int n_in,
                              void* d_out, int out_size)
{
    const float* x      = (const float*)d_in[0];
    const int*   mask   = (const int*)d_in[1];
    const float* qkv_w  = (const float*)d_in[2];
    const float* qkv_b  = (const float*)d_in[3];
    const float* proj_w = (const float*)d_in[4];
    const float* proj_b = (const float*)d_in[5];
    float* out = (float*)d_out;

    float *qkv_p, *att_p, *x_p, *wq_p, *wp_p;
    cudaGetSymbolAddress((void**)&qkv_p, g_qkv);
    cudaGetSymbolAddress((void**)&att_p, g_att);
    cudaGetSymbolAddress((void**)&x_p,  g_x);
    cudaGetSymbolAddress((void**)&wq_p, g_wq);
    cudaGetSymbolAddress((void**)&wp_p, g_wp);

    cudaFuncSetAttribute(gemm_tf32_v3, cudaFuncAttributeMaxDynamicSharedMemorySize,
                         G_SMEM_BYTES);
    cudaFuncSetAttribute(flash_attn_v4, cudaFuncAttributeMaxDynamicSharedMemorySize,
                         FA_SMEM_BYTES);

    // 0) Pre-round + k-permute inputs (one launch; counts in 8-float groups)
    round_perm3<<<512, 256>>>(x, x_p, B_ * S_ * E_ / 8,
                              qkv_w, wq_p, 3 * E_ * E_ / 8,
                              proj_w, wp_p, E_ * E_ / 8);

    // 1) QKV GEMM: permuted inputs, logical output (rounded)
    gemm_tf32_v3<<<dim3(3 * E_ / 128, B_ * S_ / 64), 256, G_SMEM_BYTES>>>(
        x_p, wq_p, qkv_b, qkv_p, B_ * S_, 3 * E_, E_, 1);

    // 2) Flash attention -> g_att (tf32-rounded, k-permuted columns)
    flash_attn_v4<<<dim3(S_ / 256, H_, B_), 512, FA_SMEM_BYTES>>>(mask);

    // 3) Proj GEMM: permuted inputs (g_att + wp), logical output
    gemm_tf32_v3<<<dim3(E_ / 128, B_ * S_ / 64), 256, G_SMEM_BYTES>>>(
        att_p, wp_p, proj_b, out, B_ * S_, E_, E_, 0);
}

// round 14
// speedup vs baseline: 1.0906x; 1.0347x over previous
#include <cuda_runtime.h>
#include <math.h>
#include <stdint.h>

#define B_ 2
#define S_ 2048
#define E_ 1024
#define H_ 16
#define D_ 64

// Scratch (allocation-free rule: __device__ globals)
// g_x/g_wq/g_wp: tf32-rounded + 8-group k(column)-permuted [0,4,1,5,2,6,3,7]
// g_wq additionally has ROWS of the q/k sections (rows < 2E) permuted within
//   8-row groups -> QKV GEMM emits d-permuted q/k sections for free.
// g_bias: qkv_b with q/k entries permuted to match.
// g_qkv: GEMM output (q/k sections d-permuted, v logical), tf32-rounded
// g_att: tf32-rounded + k-permuted columns (proj's A operand)
__device__ float g_qkv[(size_t)B_ * S_ * 3 * E_];
__device__ float g_att[(size_t)B_ * S_ * E_];
__device__ float g_x [(size_t)B_ * S_ * E_];
__device__ float g_wq[(size_t)3 * E_ * E_];
__device__ float g_wp[(size_t)E_ * E_];
__device__ float g_bias[3 * E_];

// ---------------------------------------------------------------------------
// Helpers
// ---------------------------------------------------------------------------
__device__ __forceinline__ float tf32r(float x) {
    float r;
    asm("cvt.rna.tf32.f32 %0, %1;" : "=f"(r) : "f"(x));
    return r;
}
__device__ __forceinline__ uint32_t smem_u32(const void* p) {
    uint32_t a;
    asm("{ .reg .u64 t; cvta.to.shared.u64 t, %1; cvt.u32.u64 %0, t; }"
        : "=r"(a) : "l"(p));
    return a;
}
// position of logical index c (0..7) within permuted 8-group storage
__device__ __forceinline__ int kperm(int c) {
    return (c < 4) ? (2 * c) : (2 * (c - 4) + 1);
}
// logical index stored at position p (inverse of kperm)
__device__ __forceinline__ int srcrow8(int p) {
    return (p & 1) ? (4 + (p >> 1)) : (p >> 1);
}
#define CPA16(dst, src) \
    asm volatile("cp.async.cg.shared.global [%0], [%1], 16;" :: "r"(dst), "l"(src) : "memory")
#define CPA_COMMIT() asm volatile("cp.async.commit_group;" ::: "memory")
#define CPA_WAIT0()  asm volatile("cp.async.wait_group 0;" ::: "memory")

#define MMA_TF32(d, a0, a1, a2, a3, b0, b1)                                   \
    asm volatile(                                                             \
        "mma.sync.aligned.m16n8k8.row.col.f32.tf32.tf32.f32 "                 \
        "{%0,%1,%2,%3},{%4,%5,%6,%7},{%8,%9},{%0,%1,%2,%3};"                  \
        : "+f"((d)[0]), "+f"((d)[1]), "+f"((d)[2]), "+f"((d)[3])              \
        : "r"(a0), "r"(a1), "r"(a2), "r"(a3), "r"(b0), "r"(b1))

// ---------------------------------------------------------------------------
// Prep: tf32-round + column(k)-permute x/qkv_w/proj_w; additionally permute
// ROWS of qkv_w's q/k sections within 8-row groups; permute bias to match.
// ---------------------------------------------------------------------------
__global__ void prep_all(const float* __restrict__ x,  float* __restrict__ dx,
                         const float* __restrict__ qw, float* __restrict__ dqw,
                         const float* __restrict__ pw, float* __restrict__ dpw,
                         const float* __restrict__ qb, float* __restrict__ dqb)
{
    const int NX  = B_ * S_ * E_ / 8;
    const int NQW = 3 * E_ * E_ / 8;
    const int NPW = E_ * E_ / 8;
    int i = blockIdx.x * blockDim.x + threadIdx.x;
    int stride = gridDim.x * blockDim.x;
    const int ntot = NX + NQW + NPW;
    for (int t = i; t < ntot; t += stride) {
        int j = t, sj;
        const float4* src;
        float4* dst;
        if (j < NX) {
            src = (const float4*)x; dst = (float4*)dx; sj = j;
        } else if ((j -= NX) < NQW) {
            src = (const float4*)qw; dst = (float4*)dqw;
            int n  = j >> 7;           // row (E_/8 = 128 groups per row)
            int kg = j & 127;
            int m  = (n < 2 * E_) ? ((n & ~7) | srcrow8(n & 7)) : n;
            sj = m * 128 + kg;
        } else {
            j -= NQW;
            src = (const float4*)pw; dst = (float4*)dpw; sj = j;
        }
        float4 u = src[2 * sj];       // k0..k3
        float4 v = src[2 * sj + 1];   // k4..k7
        u.x = tf32r(u.x); u.y = tf32r(u.y); u.z = tf32r(u.z); u.w = tf32r(u.w);
        v.x = tf32r(v.x); v.y = tf32r(v.y); v.z = tf32r(v.z); v.w = tf32r(v.w);
        dst[2 * j]     = make_float4(u.x, v.x, u.y, v.y);
        dst[2 * j + 1] = make_float4(u.z, v.z, u.w, v.w);
    }
    // bias: permute q/k entries within 8-groups; v straight
    for (int t = i; t < 3 * E_; t += stride) {
        int s = (t < 2 * E_) ? ((t & ~7) | srcrow8(t & 7)) : t;
        dqb[t] = qb[s];
    }
}

// ---------------------------------------------------------------------------
// GEMM v3 (unchanged from R13): 64x128 CTA tile, 32x32 warp tile, BK=32,
// k-permuted inputs -> LDS.64 fragments, 3 CTAs/SM.
// ---------------------------------------------------------------------------
#define GS_STRIDE 40
#define GA_FLOATS (64 * GS_STRIDE)
#define GB_FLOATS (128 * GS_STRIDE)
#define G_OFF_A0 0
#define G_OFF_A1 GA_FLOATS
#define G_OFF_B0 (2 * GA_FLOATS)
#define G_OFF_B1 (2 * GA_FLOATS + GB_FLOATS)
#define G_SMEM_BYTES ((2 * GA_FLOATS + 2 * GB_FLOATS) * 4)   // 61,440 B

__global__ __launch_bounds__(256, 3) void gemm_tf32_v3(
    const float* __restrict__ A, const float* __restrict__ Bm,
    const float* __restrict__ bias, float* __restrict__ C,
    int M, int N, int K, int do_round)
{
    extern __shared__ float smg[];
    const uint32_t sb = smem_u32(smg);

    const int tid  = threadIdx.x;
    const int warp = tid >> 5;
    const int lane = tid & 31;
    const int m0 = blockIdx.y * 64;
    const int n0 = blockIdx.x * 128;
    const int wm = (warp >> 2) * 32;
    const int wn = (warp & 3) * 32;
    const int r  = lane >> 2;
    const int cq = lane & 3;

    const int srow = tid >> 3;
    const int svec = tid & 7;

    float acc[2][4][4] = {};
    const int T = K >> 5;

#define GEMM_STAGE(t, buf) do {                                               \
        const int k0_ = (t) << 5;                                             \
        uint32_t abase = sb + ((buf) ? G_OFF_A1 : G_OFF_A0) * 4;              \
        uint32_t bbase = sb + ((buf) ? G_OFF_B1 : G_OFF_B0) * 4;              \
        _Pragma("unroll")                                                     \
        for (int u = 0; u < 2; ++u) {                                         \
            int row = srow + u * 32;                                          \
            uint32_t da = abase + (row * GS_STRIDE + svec * 4) * 4;           \
            CPA16(da, A + (size_t)(m0 + row) * K + k0_ + svec * 4);           \
        }                                                                     \
        _Pragma("unroll")                                                     \
        for (int u = 0; u < 4; ++u) {                                         \
            int row = srow + u * 32;                                          \
            uint32_t db = bbase + (row * GS_STRIDE + svec * 4) * 4;           \
            CPA16(db, Bm + (size_t)(n0 + row) * K + k0_ + svec * 4);          \
        }                                                                     \
    } while (0)

    GEMM_STAGE(0, 0);
    CPA_COMMIT();
    CPA_WAIT0();
    __syncthreads();

    for (int t = 0; t < T; ++t) {
        const int buf = t & 1;
        if (t + 1 < T) {
            GEMM_STAGE(t + 1, buf ^ 1);
            CPA_COMMIT();
        }

        const float* Asb = smg + (buf ? G_OFF_A1 : G_OFF_A0);
        const float* Bsb = smg + (buf ? G_OFF_B1 : G_OFF_B0);
#pragma unroll
        for (int ks = 0; ks < 4; ++ks) {
            const int kb2 = ks * 8 + 2 * cq;
            unsigned a[2][4], b[4][2];
#pragma unroll
            for (int mt = 0; mt < 2; ++mt) {
                int row = wm + mt * 16 + r;
                float2 f0 = *(const float2*)&Asb[row * GS_STRIDE + kb2];
                float2 f1 = *(const float2*)&Asb[(row + 8) * GS_STRIDE + kb2];
                a[mt][0] = __float_as_uint(f0.x);
                a[mt][1] = __float_as_uint(f1.x);
                a[mt][2] = __float_as_uint(f0.y);
                a[mt][3] = __float_as_uint(f1.y);
            }
#pragma unroll
            for (int nt = 0; nt < 4; ++nt) {
                float2 f = *(const float2*)&Bsb[(wn + nt * 8 + r) * GS_STRIDE + kb2];
                b[nt][0] = __float_as_uint(f.x);
                b[nt][1] = __float_as_uint(f.y);
            }
#pragma unroll
            for (int mt = 0; mt < 2; ++mt)
#pragma unroll
                for (int nt = 0; nt < 4; ++nt)
                    MMA_TF32(acc[mt][nt], a[mt][0], a[mt][1], a[mt][2], a[mt][3],
                             b[nt][0], b[nt][1]);
        }

        if (t + 1 < T) {
            CPA_WAIT0();
            __syncthreads();
        }
    }
#undef GEMM_STAGE

    const int c2 = cq * 2;
#pragma unroll
    for (int nt = 0; nt < 4; ++nt) {
        int col = n0 + wn + nt * 8 + c2;
        float b0 = bias[col], b1 = bias[col + 1];
#pragma unroll
        for (int mt = 0; mt < 2; ++mt) {
            int row = m0 + wm + mt * 16 + r;
            float v00 = acc[mt][nt][0] + b0, v01 = acc[mt][nt][1] + b1;
            float v10 = acc[mt][nt][2] + b0, v11 = acc[mt][nt][3] + b1;
            if (do_round) {
                v00 = tf32r(v00); v01 = tf32r(v01);
                v10 = tf32r(v10); v11 = tf32r(v11);
            }
            *(float2*)(C + (size_t)row * N + col)       = make_float2(v00, v01);
            *(float2*)(C + (size_t)(row + 8) * N + col) = make_float2(v10, v11);
        }
    }
}

// ---------------------------------------------------------------------------
// Flash attention v6: Q/K sections of g_qkv are d-permuted -> Q-hoist and K
// fragment loads are float2 (LDS.64). K/Q smem stride 72 (conflict-free
// float2), V stride 68 (conflict-free scalar). Otherwise identical to R13.
// ---------------------------------------------------------------------------
#define QST 72
#define VST 68
#define FQ_FLOATS (256 * QST)                    // 18432
#define FK_FLOATS (128 * QST)                    // 9216 per buf
#define FV_FLOATS (128 * VST)                    // 8704 per buf
#define OFF_K  FQ_FLOATS
#define OFF_V  (FQ_FLOATS + 2 * FK_FLOATS)
#define OFF_MK (FQ_FLOATS + 2 * FK_FLOATS + 2 * FV_FLOATS)
#define FA_SMEM_BYTES ((OFF_MK + 2 * 128) * 4)   // 218,112 B

__global__ __launch_bounds__(512, 1) void flash_attn_v6(const int* __restrict__ mask)
{
    extern __shared__ float sm[];
    const uint32_t sb = smem_u32(sm);

    const int tid  = threadIdx.x;
    const int warp = tid >> 5;
    const int lane = tid & 31;
    const int q0 = blockIdx.x * 256;
    const int h  = blockIdx.y;
    const int b  = blockIdx.z;
    const int wq = warp * 16;
    const int r  = lane >> 2;
    const int cq = lane & 3;
    const int qrow = wq + r;

    const size_t rowstride = (size_t)3 * E_;

    {
        const float* qb = g_qkv + (size_t)(b * S_ + q0) * rowstride + h * D_;
#pragma unroll
        for (int u = 0; u < 8; ++u) {
            int idx = tid + u * 512;
            int row = idx >> 4;
            int vec = idx & 15;
            uint32_t dq = sb + (row * QST + vec * 4) * 4;
            CPA16(dq, qb + (size_t)row * rowstride + vec * 4);
        }
    }

#define FA_STAGE(t, buf) do {                                                 \
        const int k0_ = (t) * 128;                                            \
        const float* kb = g_qkv + (size_t)(b * S_ + k0_) * rowstride + E_ + h * D_; \
        _Pragma("unroll")                                                     \
        for (int u = 0; u < 4; ++u) {                                         \
            int idx = tid + u * 512;                                          \
            int row = idx >> 4;                                               \
            int vec = idx & 15;                                               \
            uint32_t dk = sb + ((OFF_K + (buf) * FK_FLOATS) + row * QST + vec * 4) * 4; \
            CPA16(dk, kb + (size_t)row * rowstride + vec * 4);                \
            uint32_t dv = sb + ((OFF_V + (buf) * FV_FLOATS) + row * VST + vec * 4) * 4; \
            CPA16(dv, kb + E_ + (size_t)row * rowstride + vec * 4);           \
        }                                                                     \
        if (tid < 128)                                                        \
            sm[OFF_MK + (buf) * 128 + tid] =                                  \
                mask[b * S_ + k0_ + tid] ? 0.f : -INFINITY;                   \
    } while (0)

    FA_STAGE(0, 0);
    CPA_COMMIT();
    CPA_WAIT0();
    __syncthreads();

    // ---- Hoist Q fragments (float2; permuted d) ----
    unsigned qa[8][4];
#pragma unroll
    for (int ks = 0; ks < 8; ++ks) {
        const int kb2 = ks * 8 + 2 * cq;
        float2 f0 = *(const float2*)&sm[qrow * QST + kb2];
        float2 f1 = *(const float2*)&sm[(qrow + 8) * QST + kb2];
        qa[ks][0] = __float_as_uint(f0.x);
        qa[ks][1] = __float_as_uint(f1.x);
        qa[ks][2] = __float_as_uint(f0.y);
        qa[ks][3] = __float_as_uint(f1.y);
    }

    float o[8][4] = {};
    float m0 = -INFINITY, m1 = -INFINITY, l0 = 0.f, l1 = 0.f;

    const int T = S_ / 128;
    for (int t = 0; t < T; ++t) {
        const int buf = t & 1;
        if (t + 1 < T) {
            FA_STAGE(t + 1, buf ^ 1);
            CPA_COMMIT();
        }

#pragma unroll
        for (int half = 0; half < 2; ++half) {
            const float* Ksb = sm + OFF_K + buf * FK_FLOATS + (half * 64) * QST;
            const float* Vsb = sm + OFF_V + buf * FV_FLOATS + (half * 64) * VST;
            const float* mkb = sm + OFF_MK + buf * 128 + half * 64;

            // ---- S = Q K^T (float2 K fragments) ----
            float s[8][4] = {};
#pragma unroll
            for (int ks = 0; ks < 8; ++ks) {
                const int kb2 = ks * 8 + 2 * cq;
#pragma unroll
                for (int nt = 0; nt < 8; ++nt) {
                    float2 fk = *(const float2*)&Ksb[(nt * 8 + r) * QST + kb2];
                    MMA_TF32(s[nt], qa[ks][0], qa[ks][1], qa[ks][2], qa[ks][3],
                             __float_as_uint(fk.x), __float_as_uint(fk.y));
                }
            }

#pragma unroll
            for (int nt = 0; nt < 8; ++nt) {
                float mk0 = mkb[nt * 8 + 2 * cq];
                float mk1 = mkb[nt * 8 + 2 * cq + 1];
                s[nt][0] = fmaf(s[nt][0], 0.125f, mk0);
                s[nt][1] = fmaf(s[nt][1], 0.125f, mk1);
                s[nt][2] = fmaf(s[nt][2], 0.125f, mk0);
                s[nt][3] = fmaf(s[nt][3], 0.125f, mk1);
            }

            float mx0 = -INFINITY, mx1 = -INFINITY;
#pragma unroll
            for (int nt = 0; nt < 8; ++nt) {
                mx0 = fmaxf(mx0, fmaxf(s[nt][0], s[nt][1]));
                mx1 = fmaxf(mx1, fmaxf(s[nt][2], s[nt][3]));
            }
            mx0 = fmaxf(mx0, __shfl_xor_sync(0xffffffffu, mx0, 1));
            mx0 = fmaxf(mx0, __shfl_xor_sync(0xffffffffu, mx0, 2));
            mx1 = fmaxf(mx1, __shfl_xor_sync(0xffffffffu, mx1, 1));
            mx1 = fmaxf(mx1, __shfl_xor_sync(0xffffffffu, mx1, 2));

            float mn0 = fmaxf(m0, mx0);
            float mn1 = fmaxf(m1, mx1);
            float al0 = 1.f, al1 = 1.f;
            float ls0 = 0.f, ls1 = 0.f;
            if (mn0 != -INFINITY) {
                al0 = __expf(m0 - mn0);
#pragma unroll
                for (int nt = 0; nt < 8; ++nt) {
                    float p0 = __expf(s[nt][0] - mn0);
                    float p1 = __expf(s[nt][1] - mn0);
                    ls0 += p0 + p1;
                    s[nt][0] = tf32r(p0);
                    s[nt][1] = tf32r(p1);
                }
            } else {
#pragma unroll
                for (int nt = 0; nt < 8; ++nt) { s[nt][0] = 0.f; s[nt][1] = 0.f; }
            }
            if (mn1 != -INFINITY) {
                al1 = __expf(m1 - mn1);
#pragma unroll
                for (int nt = 0; nt < 8; ++nt) {
                    float p2 = __expf(s[nt][2] - mn1);
                    float p3 = __expf(s[nt][3] - mn1);
                    ls1 += p2 + p3;
                    s[nt][2] = tf32r(p2);
                    s[nt][3] = tf32r(p3);
                }
            } else {
#pragma unroll
                for (int nt = 0; nt < 8; ++nt) { s[nt][2] = 0.f; s[nt][3] = 0.f; }
            }
            ls0 += __shfl_xor_sync(0xffffffffu, ls0, 1);
            ls0 += __shfl_xor_sync(0xffffffffu, ls0, 2);
            ls1 += __shfl_xor_sync(0xffffffffu, ls1, 1);
            ls1 += __shfl_xor_sync(0xffffffffu, ls1, 2);

            l0 = l0 * al0 + ls0;  m0 = mn0;
            l1 = l1 * al1 + ls1;  m1 = mn1;

#pragma unroll
            for (int nt = 0; nt < 8; ++nt) {
                o[nt][0] *= al0; o[nt][1] *= al0;
                o[nt][2] *= al1; o[nt][3] *= al1;
            }

#pragma unroll
            for (int ks = 0; ks < 8; ++ks) {
                unsigned pa0 = __float_as_uint(s[ks][0]);
                unsigned pa1 = __float_as_uint(s[ks][2]);
                unsigned pa2 = __float_as_uint(s[ks][1]);
                unsigned pa3 = __float_as_uint(s[ks][3]);
                const float* vrow0 = Vsb + (ks * 8 + 2 * cq) * VST;
#pragma unroll
                for (int nt = 0; nt < 8; ++nt) {
                    unsigned vb0 = __float_as_uint(vrow0[nt * 8 + r]);
                    unsigned vb1 = __float_as_uint(vrow0[VST + nt * 8 + r]);
                    MMA_TF32(o[nt], pa0, pa1, pa2, pa3, vb0, vb1);
                }
            }
        }

        if (t + 1 < T) {
            CPA_WAIT0();
            __syncthreads();
        }
    }
#undef FA_STAGE

    // ---- normalize + tf32 round + store (k-permuted columns for proj) ----
    float inv0 = (l0 > 0.f) ? (1.f / l0) : 0.f;
    float inv1 = (l1 > 0.f) ? (1.f / l1) : 0.f;
    float* d0 = g_att + (size_t)(b * S_ + q0 + qrow) * E_ + h * D_;
    float* d1 = g_att + (size_t)(b * S_ + q0 + qrow + 8) * E_ + h * D_;
    const int pp0 = kperm(2 * cq);
    const int pp1 = kperm(2 * cq + 1);
#pragma unroll
    for (int nt = 0; nt < 8; ++nt) {
        d0[nt * 8 + pp0] = tf32r(o[nt][0] * inv0);
        d0[nt * 8 + pp1] = tf32r(o[nt][1] * inv0);
        d1[nt * 8 + pp0] = tf32r(o[nt][2] * inv1);
        d1[nt * 8 + pp1] = tf32r(o[nt][3] * inv1);
    }
}

// ---------------------------------------------------------------------------
extern "C" void kernel_launch(void* const* d_in, const int* in_sizes, int n_in,
                              void* d_out, int out_size)
{
    const float* x      = (const float*)d_in[0];
    const int*   mask   = (const int*)d_in[1];
    const float* qkv_w  = (const float*)d_in[2];
    const float* qkv_b  = (const float*)d_in[3];
    const float* proj_w = (const float*)d_in[4];
    const float* proj_b = (const float*)d_in[5];
    float* out = (float*)d_out;

    float *qkv_p, *att_p, *x_p, *wq_p, *wp_p, *bias_p;
    cudaGetSymbolAddress((void**)&qkv_p, g_qkv);
    cudaGetSymbolAddress((void**)&att_p, g_att);
    cudaGetSymbolAddress((void**)&x_p,  g_x);
    cudaGetSymbolAddress((void**)&wq_p, g_wq);
    cudaGetSymbolAddress((void**)&wp_p, g_wp);
    cudaGetSymbolAddress((void**)&bias_p, g_bias);

    cudaFuncSetAttribute(gemm_tf32_v3, cudaFuncAttributeMaxDynamicSharedMemorySize,
                         G_SMEM_BYTES);
    cudaFuncSetAttribute(flash_attn_v6, cudaFuncAttributeMaxDynamicSharedMemorySize,
                         FA_SMEM_BYTES);

    // 0) Prep: round+col-permute all inputs; row-permute Wq/Wk + bias q/k
    prep_all<<<512, 256>>>(x, x_p, qkv_w, wq_p, proj_w, wp_p, qkv_b, bias_p);

    // 1) QKV GEMM: permuted inputs, output q/k sections d-permuted (rounded)
    gemm_tf32_v3<<<dim3(3 * E_ / 128, B_ * S_ / 64), 256, G_SMEM_BYTES>>>(
        x_p, wq_p, bias_p, qkv_p, B_ * S_, 3 * E_, E_, 1);

    // 2) Flash attention -> g_att (tf32-rounded, k-permuted columns)
    flash_attn_v6<<<dim3(S_ / 256, H_, B_), 512, FA_SMEM_BYTES>>>(mask);

    // 3) Proj GEMM: permuted inputs (g_att + wp), logical output
    gemm_tf32_v3<<<dim3(E_ / 128, B_ * S_ / 64), 256, G_SMEM_BYTES>>>(
        att_p, wp_p, proj_b, out, B_ * S_, E_, E_, 0);
}